// round 16
// baseline (speedup 1.0000x reference)
#include <cuda_runtime.h>
#include <cuda_fp16.h>
#include <math.h>
#include <stdint.h>

// ---------------------------------------------------------------------------
// feat [T=32768, 2048] f32; w1[64,32] b1[32] w2[32,1] b2[1];
// wp [1024, 2048] f32; bp [2048]; out [T, 2048] f32.
//   K1: score MLP + top-16 + fused gather/fp16 emission (R8/R10 validated).
//   KW: wp -> W_T fp16, smem-tiled transpose (R15).
//   KG: mma.sync fp16 GEMM. CTA 128x256, 8 warps of 64x64, 1 CTA/SM
//       (255-reg cap -> ptxas can pipeline fragments), 2-stage cp.async,
//       one __syncthreads per chunk. K-accumulation order unchanged.
// ---------------------------------------------------------------------------

#define T_MAX 32768

__device__ __half g_Phi[T_MAX * 1024];    // 64 MB   [M,K]
__device__ __half g_WT[2048 * 1024];      // 4 MB    [N,K]

__device__ __forceinline__ uint32_t smem_u32(const void* p) {
    uint32_t a;
    asm("{ .reg .u64 t; cvta.to.shared.u64 t, %1; cvt.u32.u64 %0, t; }"
        : "=r"(a) : "l"(p));
    return a;
}

// ---------------------------------------------------------------------------
// K1: scores + top-16 + emission, 2 tokens per warp, lane = node. (R10)
// ---------------------------------------------------------------------------
__device__ __forceinline__ unsigned fkey(float x) {
    unsigned u = __float_as_uint(x);
    return (u & 0x80000000u) ? ~u : (u | 0x80000000u);
}

__device__ __forceinline__ void emit_row(const float* ndf, size_t slot) {
    uint4* ph = reinterpret_cast<uint4*>(g_Phi + slot * 64);
    #pragma unroll
    for (int i = 0; i < 8; i++) {
        unsigned hw[4];
        #pragma unroll
        for (int j = 0; j < 4; j++) {
            __half ha = __float2half_rn(ndf[i*8 + j*2]);
            __half hb = __float2half_rn(ndf[i*8 + j*2 + 1]);
            hw[j] = (unsigned)__half_as_ushort(ha) |
                    ((unsigned)__half_as_ushort(hb) << 16);
        }
        ph[i] = make_uint4(hw[0], hw[1], hw[2], hw[3]);
    }
}

__global__ void __launch_bounds__(128, 3)
k_score_topk(const float* __restrict__ feat,
             const float* __restrict__ w1,
             const float* __restrict__ b1,
             const float* __restrict__ w2,
             const float* __restrict__ b2, int T)
{
    __shared__ float4 w1s[32][16];   // row j = w1[:,j] as 16 float4
    __shared__ float b1s[32];
    __shared__ float w2s[32];
    __shared__ float b2s;

    int tid = threadIdx.x;
    for (int i = tid; i < 2048; i += 128) {
        int j = i >> 6, d = i & 63;
        reinterpret_cast<float*>(&w1s[j][0])[d] = w1[d * 32 + j];
    }
    if (tid < 32) { b1s[tid] = b1[tid]; w2s[tid] = w2[tid]; }
    if (tid == 0) b2s = b2[0];
    __syncthreads();

    int warp = tid >> 5, lane = tid & 31;
    int tA = blockIdx.x * 8 + warp * 2;
    int tB = tA + 1;
    if (tA >= T) return;
    bool hasB = (tB < T);

    float4 ndA[16], ndB[16];
    const float4* npA =
        reinterpret_cast<const float4*>(feat + (size_t)tA * 2048 + lane * 64);
    const float4* npB =
        reinterpret_cast<const float4*>(feat + (size_t)tB * 2048 + lane * 64);
    #pragma unroll
    for (int i = 0; i < 16; i++) ndA[i] = npA[i];
    if (hasB) {
        #pragma unroll
        for (int i = 0; i < 16; i++) ndB[i] = npB[i];
    }

    // Serial fmaf chain per (token, j): EXACT validated rounding order.
    float scA = b2s, scB = b2s;
    for (int j = 0; j < 32; j++) {
        float aA = b1s[j], aB = b1s[j];
        #pragma unroll
        for (int q = 0; q < 16; q++) {
            float4 w = w1s[j][q];
            aA = fmaf(ndA[q].x, w.x, aA);
            aA = fmaf(ndA[q].y, w.y, aA);
            aA = fmaf(ndA[q].z, w.z, aA);
            aA = fmaf(ndA[q].w, w.w, aA);
            aB = fmaf(ndB[q].x, w.x, aB);
            aB = fmaf(ndB[q].y, w.y, aB);
            aB = fmaf(ndB[q].z, w.z, aB);
            aB = fmaf(ndB[q].w, w.w, aB);
        }
        float gA = 0.5f * aA * (1.0f + erff(aA * 0.7071067811865476f));
        scA = fmaf(gA, w2s[j], scA);
        float gB = 0.5f * aB * (1.0f + erff(aB * 0.7071067811865476f));
        scB = fmaf(gB, w2s[j], scB);
    }

    {
        unsigned key = fkey(scA);
        int myrank = -1;
        for (int it = 0; it < 16; it++) {
            unsigned long long kv =
                ((unsigned long long)key << 6) | (unsigned)(63 - lane);
            #pragma unroll
            for (int off = 16; off; off >>= 1) {
                unsigned long long o = __shfl_xor_sync(0xffffffffu, kv, off);
                if (o > kv) kv = o;
            }
            int win = 63 - (int)(kv & 63ull);
            if (lane == win) { myrank = it; key = 0u; }
        }
        if (myrank >= 0)
            emit_row(reinterpret_cast<const float*>(ndA),
                     (size_t)tA * 16 + myrank);
    }
    if (hasB) {
        unsigned key = fkey(scB);
        int myrank = -1;
        for (int it = 0; it < 16; it++) {
            unsigned long long kv =
                ((unsigned long long)key << 6) | (unsigned)(63 - lane);
            #pragma unroll
            for (int off = 16; off; off >>= 1) {
                unsigned long long o = __shfl_xor_sync(0xffffffffu, kv, off);
                if (o > kv) kv = o;
            }
            int win = 63 - (int)(kv & 63ull);
            if (lane == win) { myrank = it; key = 0u; }
        }
        if (myrank >= 0)
            emit_row(reinterpret_cast<const float*>(ndB),
                     (size_t)tB * 16 + myrank);
    }
}

// ---------------------------------------------------------------------------
// KW: wp [1024,2048] -> W_T [2048,1024] fp16 via smem-tiled transpose. (R15)
// ---------------------------------------------------------------------------
__global__ void k_wconv(const float* __restrict__ wp)
{
    __shared__ float t[32][33];
    int tx = threadIdx.x, ty = threadIdx.y;
    int n0 = blockIdx.x * 32, k0 = blockIdx.y * 32;

    #pragma unroll
    for (int i = 0; i < 4; i++) {
        int k = ty + i * 8;
        t[k][tx] = wp[(size_t)(k0 + k) * 2048 + n0 + tx];
    }
    __syncthreads();
    #pragma unroll
    for (int i = 0; i < 4; i++) {
        int n = ty + i * 8;
        g_WT[(size_t)(n0 + n) * 1024 + k0 + tx] = __float2half_rn(t[tx][n]);
    }
}

// ---------------------------------------------------------------------------
// KG: mma.sync fp16 GEMM. CTA 128(M)x256(N), BK=64, 8 warps of 64x64,
// 2-stage cp.async (48KB/stage), 1 CTA/SM, one sync per chunk.
// ---------------------------------------------------------------------------
#define STAGE_BYTES 49152           // A 16K | W 32K
#define SMEM_TOTAL (2 * STAGE_BYTES)

__device__ __forceinline__ uint32_t swz(uint32_t base, int row, int k8) {
    return base + row * 128 + (((k8 ^ (row & 7)) << 4));
}
__device__ __forceinline__ void cp16(uint32_t s, const void* g) {
    asm volatile("cp.async.cg.shared.global [%0], [%1], 16;" :: "r"(s), "l"(g));
}
#define CP_COMMIT() asm volatile("cp.async.commit_group;" ::: "memory")
#define CP_WAIT0()  asm volatile("cp.async.wait_group 0;"  ::: "memory")

__device__ __forceinline__ void ldmx4(uint32_t* r, uint32_t a) {
    asm volatile("ldmatrix.sync.aligned.m8n8.x4.shared.b16 {%0,%1,%2,%3}, [%4];"
                 : "=r"(r[0]), "=r"(r[1]), "=r"(r[2]), "=r"(r[3]) : "r"(a));
}
__device__ __forceinline__ void mma16816(float* c, const uint32_t* a,
                                         const uint32_t* b) {
    asm("mma.sync.aligned.m16n8k16.row.col.f32.f16.f16.f32 "
        "{%0,%1,%2,%3},{%4,%5,%6,%7},{%8,%9},{%0,%1,%2,%3};"
        : "+f"(c[0]), "+f"(c[1]), "+f"(c[2]), "+f"(c[3])
        : "r"(a[0]), "r"(a[1]), "r"(a[2]), "r"(a[3]), "r"(b[0]), "r"(b[1]));
}

// A: 128 rows (1024 cp16), B: 256 rows (2048 cp16); 12 cp16/thread @256thr
__device__ __forceinline__ void load_stage(uint32_t sbase, int m0, int n0,
                                           int c, int tid) {
    const uint4* Ph = reinterpret_cast<const uint4*>(g_Phi);
    const uint4* Wh = reinterpret_cast<const uint4*>(g_WT);
    #pragma unroll
    for (int i = 0; i < 4; i++) {
        int lin = i * 256 + tid;            // 0..1023
        int row = lin >> 3, k8 = lin & 7;
        size_t gA = (size_t)(m0 + row) * 128 + c * 8 + k8;
        cp16(swz(sbase, row, k8), Ph + gA);
    }
    #pragma unroll
    for (int i = 0; i < 8; i++) {
        int lin = i * 256 + tid;            // 0..2047
        int row = lin >> 3, k8 = lin & 7;
        size_t gB = (size_t)(n0 + row) * 128 + c * 8 + k8;
        cp16(swz(sbase + 16384, row, k8), Wh + gB);
    }
}

__global__ void __launch_bounds__(256, 1)
k_gemm_mma(const float* __restrict__ bp, float* __restrict__ out)
{
    extern __shared__ char smem[];
    uint32_t sb = smem_u32(smem);
    int tid = threadIdx.x, wid = tid >> 5, lane = tid & 31;
    int n0 = blockIdx.x * 256;
    int m0 = blockIdx.y * 128;
    int wm0 = (wid & 1) * 64;
    int wn0 = (wid >> 1) * 64;

    float acc[4][8][4];
    #pragma unroll
    for (int a = 0; a < 4; a++)
        #pragma unroll
        for (int b = 0; b < 8; b++)
            #pragma unroll
            for (int q = 0; q < 4; q++) acc[a][b][q] = 0.f;

    load_stage(sb, m0, n0, 0, tid); CP_COMMIT();

    int arow = wm0 + (lane & 15);
    int ak8 = (lane >> 4);
    int brow = wn0 + ((lane >> 4) << 3) + (lane & 7);
    int bk8 = (lane >> 3) & 1;

    for (int c = 0; c < 16; c++) {
        CP_WAIT0();
        __syncthreads();   // stage c visible to all; prior reads of the
                           // other stage complete -> safe to overwrite

        if (c + 1 < 16) {
            load_stage(sb + ((c + 1) & 1) * STAGE_BYTES, m0, n0, c + 1, tid);
            CP_COMMIT();
        }

        uint32_t st = sb + (c & 1) * STAGE_BYTES;
        uint32_t Ah = st, Bh = st + 16384;
        #pragma unroll
        for (int ks = 0; ks < 4; ks++) {
            uint32_t ah[4][4], bh[4][4];
            #pragma unroll
            for (int mt = 0; mt < 4; mt++)
                ldmx4(ah[mt], swz(Ah, arow + mt * 16, ks * 2 + ak8));
            #pragma unroll
            for (int nt2 = 0; nt2 < 4; nt2++)
                ldmx4(bh[nt2], swz(Bh, brow + nt2 * 16, ks * 2 + bk8));
            #pragma unroll
            for (int mt = 0; mt < 4; mt++)
                #pragma unroll
                for (int nt = 0; nt < 8; nt++)
                    mma16816(acc[mt][nt], ah[mt], &bh[nt >> 1][(nt & 1) * 2]);
        }
    }

    int tg = lane >> 2, t4 = lane & 3;
    #pragma unroll
    for (int mt = 0; mt < 4; mt++) {
        #pragma unroll
        for (int nt = 0; nt < 8; nt++) {
            int col = n0 + wn0 + nt * 8 + t4 * 2;
            float2 b2 = *reinterpret_cast<const float2*>(bp + col);
            int r0 = m0 + wm0 + mt * 16 + tg;
            float2 v0 = make_float2(acc[mt][nt][0] + b2.x,
                                    acc[mt][nt][1] + b2.y);
            float2 v1 = make_float2(acc[mt][nt][2] + b2.x,
                                    acc[mt][nt][3] + b2.y);
            *reinterpret_cast<float2*>(out + (size_t)r0 * 2048 + col) = v0;
            *reinterpret_cast<float2*>(out + (size_t)(r0 + 8) * 2048 + col) = v1;
        }
    }
}

// ---------------------------------------------------------------------------
// Launch
// ---------------------------------------------------------------------------
extern "C" void kernel_launch(void* const* d_in, const int* in_sizes, int n_in,
                              void* d_out, int out_size)
{
    const float* feat = (const float*)d_in[0];
    const float* w1   = (const float*)d_in[1];
    const float* b1   = (const float*)d_in[2];
    const float* w2   = (const float*)d_in[3];
    const float* b2   = (const float*)d_in[4];
    const float* wp   = (const float*)d_in[5];
    const float* bp   = (const float*)d_in[6];
    float* out = (float*)d_out;

    int T = in_sizes[0] / 2048;   // 32768

    cudaFuncSetAttribute(k_gemm_mma,
                         cudaFuncAttributeMaxDynamicSharedMemorySize, SMEM_TOTAL);

    k_score_topk<<<(T + 7) / 8, 128>>>(feat, w1, b1, w2, b2, T);
    dim3 wgrid(64, 32);
    k_wconv<<<wgrid, dim3(32, 8)>>>(wp);
    dim3 grid(2048 / 256, T / 128);   // N fastest -> A rows L2-resident
    k_gemm_mma<<<grid, 256, SMEM_TOTAL>>>(bp, out);
}

// round 17
// speedup vs baseline: 1.1620x; 1.1620x over previous
#include <cuda_runtime.h>
#include <cuda_fp16.h>
#include <math.h>
#include <stdint.h>

// ---------------------------------------------------------------------------
// feat [T=32768, 2048] f32; w1[64,32] b1[32] w2[32,1] b2[1];
// wp [1024, 2048] f32; bp [2048]; out [T, 2048] f32.
//   K1: score MLP + top-16 + fused gather/fp16 emission (R8/R10 validated).
//   KW: wp -> W_T fp16, smem-tiled transpose (R15).
//   KG: mma.sync fp16 GEMM, CTA 128x128, 8 warps (64x32), 3-stage cp.async,
//       2 CTAs/SM, one sync per chunk, loads after MMAs (R15) —
//       main loop FULLY UNROLLED so stage indices constant-fold.
// ---------------------------------------------------------------------------

#define T_MAX 32768

__device__ __half g_Phi[T_MAX * 1024];    // 64 MB   [M,K]
__device__ __half g_WT[2048 * 1024];      // 4 MB    [N,K]

__device__ __forceinline__ uint32_t smem_u32(const void* p) {
    uint32_t a;
    asm("{ .reg .u64 t; cvta.to.shared.u64 t, %1; cvt.u32.u64 %0, t; }"
        : "=r"(a) : "l"(p));
    return a;
}

// ---------------------------------------------------------------------------
// K1: scores + top-16 + emission, 2 tokens per warp, lane = node. (R10)
// ---------------------------------------------------------------------------
__device__ __forceinline__ unsigned fkey(float x) {
    unsigned u = __float_as_uint(x);
    return (u & 0x80000000u) ? ~u : (u | 0x80000000u);
}

__device__ __forceinline__ void emit_row(const float* ndf, size_t slot) {
    uint4* ph = reinterpret_cast<uint4*>(g_Phi + slot * 64);
    #pragma unroll
    for (int i = 0; i < 8; i++) {
        unsigned hw[4];
        #pragma unroll
        for (int j = 0; j < 4; j++) {
            __half ha = __float2half_rn(ndf[i*8 + j*2]);
            __half hb = __float2half_rn(ndf[i*8 + j*2 + 1]);
            hw[j] = (unsigned)__half_as_ushort(ha) |
                    ((unsigned)__half_as_ushort(hb) << 16);
        }
        ph[i] = make_uint4(hw[0], hw[1], hw[2], hw[3]);
    }
}

__global__ void __launch_bounds__(128, 3)
k_score_topk(const float* __restrict__ feat,
             const float* __restrict__ w1,
             const float* __restrict__ b1,
             const float* __restrict__ w2,
             const float* __restrict__ b2, int T)
{
    __shared__ float4 w1s[32][16];   // row j = w1[:,j] as 16 float4
    __shared__ float b1s[32];
    __shared__ float w2s[32];
    __shared__ float b2s;

    int tid = threadIdx.x;
    for (int i = tid; i < 2048; i += 128) {
        int j = i >> 6, d = i & 63;
        reinterpret_cast<float*>(&w1s[j][0])[d] = w1[d * 32 + j];
    }
    if (tid < 32) { b1s[tid] = b1[tid]; w2s[tid] = w2[tid]; }
    if (tid == 0) b2s = b2[0];
    __syncthreads();

    int warp = tid >> 5, lane = tid & 31;
    int tA = blockIdx.x * 8 + warp * 2;
    int tB = tA + 1;
    if (tA >= T) return;
    bool hasB = (tB < T);

    float4 ndA[16], ndB[16];
    const float4* npA =
        reinterpret_cast<const float4*>(feat + (size_t)tA * 2048 + lane * 64);
    const float4* npB =
        reinterpret_cast<const float4*>(feat + (size_t)tB * 2048 + lane * 64);
    #pragma unroll
    for (int i = 0; i < 16; i++) ndA[i] = npA[i];
    if (hasB) {
        #pragma unroll
        for (int i = 0; i < 16; i++) ndB[i] = npB[i];
    }

    // Serial fmaf chain per (token, j): EXACT validated rounding order.
    float scA = b2s, scB = b2s;
    for (int j = 0; j < 32; j++) {
        float aA = b1s[j], aB = b1s[j];
        #pragma unroll
        for (int q = 0; q < 16; q++) {
            float4 w = w1s[j][q];
            aA = fmaf(ndA[q].x, w.x, aA);
            aA = fmaf(ndA[q].y, w.y, aA);
            aA = fmaf(ndA[q].z, w.z, aA);
            aA = fmaf(ndA[q].w, w.w, aA);
            aB = fmaf(ndB[q].x, w.x, aB);
            aB = fmaf(ndB[q].y, w.y, aB);
            aB = fmaf(ndB[q].z, w.z, aB);
            aB = fmaf(ndB[q].w, w.w, aB);
        }
        float gA = 0.5f * aA * (1.0f + erff(aA * 0.7071067811865476f));
        scA = fmaf(gA, w2s[j], scA);
        float gB = 0.5f * aB * (1.0f + erff(aB * 0.7071067811865476f));
        scB = fmaf(gB, w2s[j], scB);
    }

    {
        unsigned key = fkey(scA);
        int myrank = -1;
        for (int it = 0; it < 16; it++) {
            unsigned long long kv =
                ((unsigned long long)key << 6) | (unsigned)(63 - lane);
            #pragma unroll
            for (int off = 16; off; off >>= 1) {
                unsigned long long o = __shfl_xor_sync(0xffffffffu, kv, off);
                if (o > kv) kv = o;
            }
            int win = 63 - (int)(kv & 63ull);
            if (lane == win) { myrank = it; key = 0u; }
        }
        if (myrank >= 0)
            emit_row(reinterpret_cast<const float*>(ndA),
                     (size_t)tA * 16 + myrank);
    }
    if (hasB) {
        unsigned key = fkey(scB);
        int myrank = -1;
        for (int it = 0; it < 16; it++) {
            unsigned long long kv =
                ((unsigned long long)key << 6) | (unsigned)(63 - lane);
            #pragma unroll
            for (int off = 16; off; off >>= 1) {
                unsigned long long o = __shfl_xor_sync(0xffffffffu, kv, off);
                if (o > kv) kv = o;
            }
            int win = 63 - (int)(kv & 63ull);
            if (lane == win) { myrank = it; key = 0u; }
        }
        if (myrank >= 0)
            emit_row(reinterpret_cast<const float*>(ndB),
                     (size_t)tB * 16 + myrank);
    }
}

// ---------------------------------------------------------------------------
// KW: wp [1024,2048] -> W_T [2048,1024] fp16 via smem-tiled transpose. (R15)
// ---------------------------------------------------------------------------
__global__ void k_wconv(const float* __restrict__ wp)
{
    __shared__ float t[32][33];
    int tx = threadIdx.x, ty = threadIdx.y;
    int n0 = blockIdx.x * 32, k0 = blockIdx.y * 32;

    #pragma unroll
    for (int i = 0; i < 4; i++) {
        int k = ty + i * 8;
        t[k][tx] = wp[(size_t)(k0 + k) * 2048 + n0 + tx];
    }
    __syncthreads();
    #pragma unroll
    for (int i = 0; i < 4; i++) {
        int n = ty + i * 8;
        g_WT[(size_t)(n0 + n) * 1024 + k0 + tx] = __float2half_rn(t[tx][n]);
    }
}

// ---------------------------------------------------------------------------
// KG: mma.sync fp16 GEMM, single pass. CTA 128x128, BK=64, 8 warps (64x32),
// 3-stage cp.async, XOR swizzle, 2 CTAs/SM, ONE sync per chunk,
// loads after MMAs. Main loop fully unrolled (stage idx constant-folds).
// ---------------------------------------------------------------------------
#define STAGE_BYTES 32768           // A 16K | W 16K
#define SMEM_TOTAL (3 * STAGE_BYTES)

__device__ __forceinline__ uint32_t swz(uint32_t base, int row, int k8) {
    return base + row * 128 + (((k8 ^ (row & 7)) << 4));
}
__device__ __forceinline__ void cp16(uint32_t s, const void* g) {
    asm volatile("cp.async.cg.shared.global [%0], [%1], 16;" :: "r"(s), "l"(g));
}
#define CP_COMMIT() asm volatile("cp.async.commit_group;" ::: "memory")
#define CP_WAIT1()  asm volatile("cp.async.wait_group 1;"  ::: "memory")
#define CP_WAIT0()  asm volatile("cp.async.wait_group 0;"  ::: "memory")

__device__ __forceinline__ void ldmx4(uint32_t* r, uint32_t a) {
    asm volatile("ldmatrix.sync.aligned.m8n8.x4.shared.b16 {%0,%1,%2,%3}, [%4];"
                 : "=r"(r[0]), "=r"(r[1]), "=r"(r[2]), "=r"(r[3]) : "r"(a));
}
__device__ __forceinline__ void mma16816(float* c, const uint32_t* a,
                                         const uint32_t* b) {
    asm("mma.sync.aligned.m16n8k16.row.col.f32.f16.f16.f32 "
        "{%0,%1,%2,%3},{%4,%5,%6,%7},{%8,%9},{%0,%1,%2,%3};"
        : "+f"(c[0]), "+f"(c[1]), "+f"(c[2]), "+f"(c[3])
        : "r"(a[0]), "r"(a[1]), "r"(a[2]), "r"(a[3]), "r"(b[0]), "r"(b[1]));
}

__device__ __forceinline__ void load_stage(uint32_t sbase, int m0, int n0,
                                           int c, int tid) {
    const uint4* Ph = reinterpret_cast<const uint4*>(g_Phi);
    const uint4* Wh = reinterpret_cast<const uint4*>(g_WT);
    #pragma unroll
    for (int i = 0; i < 4; i++) {
        int lin = i * 256 + tid;            // 0..1023
        int row = lin >> 3, k8 = lin & 7;
        size_t gA = (size_t)(m0 + row) * 128 + c * 8 + k8;
        size_t gB = (size_t)(n0 + row) * 128 + c * 8 + k8;
        cp16(swz(sbase,          row, k8), Ph + gA);
        cp16(swz(sbase + 16384,  row, k8), Wh + gB);
    }
}

__global__ void __launch_bounds__(256, 2)
k_gemm_mma(const float* __restrict__ bp, float* __restrict__ out)
{
    extern __shared__ char smem[];
    uint32_t sb = smem_u32(smem);
    int tid = threadIdx.x, wid = tid >> 5, lane = tid & 31;
    int n0 = blockIdx.x * 128;
    int m0 = blockIdx.y * 128;
    int wm0 = (wid & 1) * 64;
    int wn0 = (wid >> 1) * 32;

    float acc[4][4][4];
    #pragma unroll
    for (int a = 0; a < 4; a++)
        #pragma unroll
        for (int b = 0; b < 4; b++)
            #pragma unroll
            for (int q = 0; q < 4; q++) acc[a][b][q] = 0.f;

    load_stage(sb,               m0, n0, 0, tid); CP_COMMIT();
    load_stage(sb + STAGE_BYTES, m0, n0, 1, tid); CP_COMMIT();

    int arow = wm0 + (lane & 15);
    int ak8 = (lane >> 4);
    int brow = wn0 + ((lane >> 4) << 3) + (lane & 7);
    int bk8 = (lane >> 3) & 1;

    #pragma unroll
    for (int c = 0; c < 16; c++) {
        if (c < 15) CP_WAIT1(); else CP_WAIT0();
        __syncthreads();

        uint32_t st = sb + (c % 3) * STAGE_BYTES;   // constant after unroll
        uint32_t Ah = st, Bh = st + 16384;
        #pragma unroll
        for (int ks = 0; ks < 4; ks++) {
            uint32_t ah[4][4], bh[2][4];
            #pragma unroll
            for (int mt = 0; mt < 4; mt++)
                ldmx4(ah[mt], swz(Ah, arow + mt * 16, ks * 2 + ak8));
            #pragma unroll
            for (int nt2 = 0; nt2 < 2; nt2++)
                ldmx4(bh[nt2], swz(Bh, brow + nt2 * 16, ks * 2 + bk8));
            #pragma unroll
            for (int mt = 0; mt < 4; mt++)
                #pragma unroll
                for (int nt = 0; nt < 4; nt++)
                    mma16816(acc[mt][nt], ah[mt], &bh[nt >> 1][(nt & 1) * 2]);
        }

        if (c + 2 < 16) {
            load_stage(sb + ((c + 2) % 3) * STAGE_BYTES, m0, n0, c + 2, tid);
            CP_COMMIT();
        }
    }

    int tg = lane >> 2, t4 = lane & 3;
    #pragma unroll
    for (int mt = 0; mt < 4; mt++) {
        #pragma unroll
        for (int nt = 0; nt < 4; nt++) {
            int col = n0 + wn0 + nt * 8 + t4 * 2;
            float2 b2 = *reinterpret_cast<const float2*>(bp + col);
            int r0 = m0 + wm0 + mt * 16 + tg;
            float2 v0 = make_float2(acc[mt][nt][0] + b2.x,
                                    acc[mt][nt][1] + b2.y);
            float2 v1 = make_float2(acc[mt][nt][2] + b2.x,
                                    acc[mt][nt][3] + b2.y);
            *reinterpret_cast<float2*>(out + (size_t)r0 * 2048 + col) = v0;
            *reinterpret_cast<float2*>(out + (size_t)(r0 + 8) * 2048 + col) = v1;
        }
    }
}

// ---------------------------------------------------------------------------
// Launch
// ---------------------------------------------------------------------------
extern "C" void kernel_launch(void* const* d_in, const int* in_sizes, int n_in,
                              void* d_out, int out_size)
{
    const float* feat = (const float*)d_in[0];
    const float* w1   = (const float*)d_in[1];
    const float* b1   = (const float*)d_in[2];
    const float* w2   = (const float*)d_in[3];
    const float* b2   = (const float*)d_in[4];
    const float* wp   = (const float*)d_in[5];
    const float* bp   = (const float*)d_in[6];
    float* out = (float*)d_out;

    int T = in_sizes[0] / 2048;   // 32768

    cudaFuncSetAttribute(k_gemm_mma,
                         cudaFuncAttributeMaxDynamicSharedMemorySize, SMEM_TOTAL);

    k_score_topk<<<(T + 7) / 8, 128>>>(feat, w1, b1, w2, b2, T);
    dim3 wgrid(64, 32);
    k_wconv<<<wgrid, dim3(32, 8)>>>(wp);
    dim3 grid(2048 / 128, T / 128);   // N fastest -> A rows L2-resident
    k_gemm_mma<<<grid, 256, SMEM_TOTAL>>>(bp, out);
}